// round 5
// baseline (speedup 1.0000x reference)
#include <cuda_runtime.h>
#include <math.h>

#define DH 64
#define DC 3

typedef unsigned long long ull;

// Precomputed skew-symmetrized generators: 0.5*(L_k - L_k^T), [3][64][64]
__device__ float g_skew[DC * DH * DH];

__global__ void build_skew_kernel(const float* __restrict__ L) {
    int idx = blockIdx.x * blockDim.x + threadIdx.x;
    if (idx < DC * DH * DH) {
        int k   = idx / (DH * DH);
        int rem = idx - k * (DH * DH);
        int r   = rem >> 6;
        int c   = rem & 63;
        g_skew[idx] = 0.5f * (L[k * DH * DH + r * DH + c] -
                              L[k * DH * DH + c * DH + r]);
    }
}

__constant__ float c_invj[36] = {
    0.0f, 1.0f, 1.0f/2.0f, 1.0f/3.0f, 1.0f/4.0f, 1.0f/5.0f, 1.0f/6.0f, 1.0f/7.0f,
    1.0f/8.0f, 1.0f/9.0f, 1.0f/10.0f, 1.0f/11.0f, 1.0f/12.0f, 1.0f/13.0f,
    1.0f/14.0f, 1.0f/15.0f, 1.0f/16.0f, 1.0f/17.0f, 1.0f/18.0f, 1.0f/19.0f,
    1.0f/20.0f, 1.0f/21.0f, 1.0f/22.0f, 1.0f/23.0f, 1.0f/24.0f, 1.0f/25.0f,
    1.0f/26.0f, 1.0f/27.0f, 1.0f/28.0f, 1.0f/29.0f, 1.0f/30.0f, 1.0f/31.0f,
    1.0f/32.0f, 1.0f/33.0f, 1.0f/34.0f, 1.0f/35.0f
};

// ---- packed f32x2 helpers ----
__device__ __forceinline__ ull pack2(float lo, float hi) {
    float2 t = make_float2(lo, hi);
    return *reinterpret_cast<ull*>(&t);
}
__device__ __forceinline__ float2 unpack2(ull v) {
    return *reinterpret_cast<float2*>(&v);
}
__device__ __forceinline__ void ffma2(ull& d, ull a, ull b) {
    asm("fma.rn.f32x2 %0, %1, %2, %0;" : "+l"(d) : "l"(a), "l"(b));
}
__device__ __forceinline__ ull mul2(ull a, ull b) {
    ull r; asm("mul.rn.f32x2 %0, %1, %2;" : "=l"(r) : "l"(a), "l"(b));
    return r;
}
__device__ __forceinline__ ull add2(ull a, ull b) {
    ull r; asm("add.rn.f32x2 %0, %1, %2;" : "=l"(r) : "l"(a), "l"(b));
    return r;
}

__device__ __forceinline__ float warp_max(float v) {
    #pragma unroll
    for (int off = 16; off >= 1; off >>= 1)
        v = fmaxf(v, __shfl_xor_sync(0xffffffffu, v, off));
    return v;
}
__device__ __forceinline__ float warp_sum(float v) {
    #pragma unroll
    for (int off = 16; off >= 1; off >>= 1)
        v += __shfl_xor_sync(0xffffffffu, v, off);
    return v;
}

// One warp (32-thread block) per (b,s) position.
// Lane l: k = l&15, h = l>>4. Owns rows 4k..4k+3 over column half [32h, 32h+32).
#define HPAD 36   // floats between half-vector bases (bank-offset the two broadcasts)

__global__ __launch_bounds__(32, 13)
void liepe_expmv_kernel(const float* __restrict__ x,
                        const float* __restrict__ rg,
                        const float* __restrict__ Psp,
                        float* __restrict__ out)
{
    __shared__ __align__(16) float sv[2][2 * HPAD];

    const int l = threadIdx.x;
    const int k = l & 15;
    const int h = l >> 4;
    const int pos = blockIdx.x;
    const int colbase = h * 32;
    const int physoff = h * HPAD;
    const int off4 = 4 * k + ((k >= 8) ? (HPAD - 32) : 0);

    const float r0 = __ldg(&rg[pos * DC + 0]);
    const float r1 = __ldg(&rg[pos * DC + 1]);
    const float r2 = __ldg(&rg[pos * DC + 2]);

    // ---- stage x ----
    sv[0][l]        = x[pos * DH + l];
    sv[0][HPAD + l] = x[pos * DH + 32 + l];
    __syncwarp();

    // ---- y = P_sp @ x : rows 4k..4k+3 over column half, shfl-combine ----
    float y[4];
    {
        const float4* vh = reinterpret_cast<const float4*>(&sv[0][physoff]);
        #pragma unroll
        for (int r = 0; r < 4; r++) {
            const float4* pr = reinterpret_cast<const float4*>(
                Psp + (4 * k + r) * DH + colbase);
            float d = 0.f;
            #pragma unroll
            for (int q = 0; q < 8; q++) {
                float4 pv = __ldg(&pr[q]);
                float4 vq = vh[q];
                d = fmaf(pv.x, vq.x, fmaf(pv.y, vq.y,
                    fmaf(pv.z, vq.z, fmaf(pv.w, vq.w, d))));
            }
            y[r] = d;
        }
        #pragma unroll
        for (int r = 0; r < 4; r++)
            y[r] += __shfl_xor_sync(0xffffffffu, y[r], 16);
    }
    __syncwarp();

    // ---- build A rows (4k+r, col half h), packed f32x2; F-norm + inf-norm ----
    ull A[64];                 // row r occupies A[16r .. 16r+15]
    float fs = 0.f;
    float mrow = 0.f;
    #pragma unroll
    for (int r = 0; r < 4; r++) {
        const int row = 4 * k + r;
        const float4* s0 = reinterpret_cast<const float4*>(
            g_skew + (0 * DH + row) * DH + colbase);
        const float4* s1 = reinterpret_cast<const float4*>(
            g_skew + (1 * DH + row) * DH + colbase);
        const float4* s2 = reinterpret_cast<const float4*>(
            g_skew + (2 * DH + row) * DH + colbase);
        float rs = 0.f;
        #pragma unroll
        for (int q = 0; q < 8; q++) {
            float4 v0 = __ldg(&s0[q]);
            float4 v1 = __ldg(&s1[q]);
            float4 v2 = __ldg(&s2[q]);
            float ax = fmaf(r2, v2.x, fmaf(r1, v1.x, r0 * v0.x));
            float ay = fmaf(r2, v2.y, fmaf(r1, v1.y, r0 * v0.y));
            float az = fmaf(r2, v2.z, fmaf(r1, v1.z, r0 * v0.z));
            float aw = fmaf(r2, v2.w, fmaf(r1, v1.w, r0 * v0.w));
            rs += fabsf(ax) + fabsf(ay) + fabsf(az) + fabsf(aw);
            fs = fmaf(ax, ax, fmaf(ay, ay, fmaf(az, az, fmaf(aw, aw, fs))));
            A[r * 16 + 2 * q]     = pack2(ax, ay);
            A[r * 16 + 2 * q + 1] = pack2(az, aw);
        }
        rs += __shfl_xor_sync(0xffffffffu, rs, 16);
        mrow = fmaxf(mrow, rs);
    }
    float ninf = warp_max(mrow);                 // rigorous upper bound on ||A||_2
    float F2   = warp_sum(fs);                   // ||A||_F^2

    // Spectral estimate: semicircle edge ~0.252*||A||_F; 0.285 = +13% safety.
    float est = fminf(ninf, 0.285f * sqrtf(F2));
    est = fmaxf(est, 1e-8f);

    int m = (int)ceilf(est * 0.125f);            // theta = 8
    if (m < 1)  m = 1;
    if (m > 32) m = 32;
    float te = est / (float)m;
    // remainder target ~3e-5
    int p = (te <= 2.0f) ? 11 : (te <= 3.0f) ? 14 : (te <= 4.0f) ? 17
          : (te <= 5.0f) ? 20 : (te <= 6.0f) ? 23 : (te <= 6.9f) ? 25
          : (te <= 7.5f) ? 27 : 28;

    // scale A -> A/m
    if (m > 1) {
        float s = 1.0f / (float)m;
        ull sp = pack2(s, s);
        #pragma unroll
        for (int q = 0; q < 64; q++) A[q] = mul2(A[q], sp);
    }

    // ---- Taylor: y = (exp(A/m))^m y ----
    int cur = 0;
    if (h == 0)
        *reinterpret_cast<float4*>(&sv[0][off4]) =
            make_float4(y[0], y[1], y[2], y[3]);
    __syncwarp();

    for (int step = 0; step < m; step++) {
        const bool laststep = (step + 1 == m);
        for (int j = 1; j <= p; j++) {
            const ulonglong2* vv =
                reinterpret_cast<const ulonglong2*>(&sv[cur][physoff]);
            ull acc0[4] = {0ull, 0ull, 0ull, 0ull};
            ull acc1[4] = {0ull, 0ull, 0ull, 0ull};
            #pragma unroll
            for (int q = 0; q < 8; q++) {
                ulonglong2 t = vv[q];
                #pragma unroll
                for (int r = 0; r < 4; r++) {
                    ffma2(acc0[r], A[r * 16 + 2 * q],     t.x);
                    ffma2(acc1[r], A[r * 16 + 2 * q + 1], t.y);
                }
            }
            const bool lastj = (j == p);
            float ij = c_invj[j];
            float t4[4];
            #pragma unroll
            for (int r = 0; r < 4; r++) {
                float2 f = unpack2(add2(acc0[r], acc1[r]));
                float pr = f.x + f.y;
                pr += __shfl_xor_sync(0xffffffffu, pr, 16);
                t4[r] = pr * ij;
                y[r] += t4[r];
            }
            if (lastj && laststep) break;       // no more consumers of v
            if (h == 0) {
                // last Taylor term of a step stores y (v := y for next step)
                float4 st = lastj ? make_float4(y[0], y[1], y[2], y[3])
                                  : make_float4(t4[0], t4[1], t4[2], t4[3]);
                *reinterpret_cast<float4*>(&sv[cur ^ 1][off4]) = st;
            }
            __syncwarp();
            cur ^= 1;
        }
    }

    if (h == 0)
        *reinterpret_cast<float4*>(&out[pos * DH + 4 * k]) =
            make_float4(y[0], y[1], y[2], y[3]);
}

extern "C" void kernel_launch(void* const* d_in, const int* in_sizes, int n_in,
                              void* d_out, int out_size)
{
    const float* x = (const float*)d_in[0];   // [B,S,64]
    const float* r = (const float*)d_in[1];   // [B,S,3]
    const float* L = (const float*)d_in[2];   // [3,64,64]
    const float* P = (const float*)d_in[3];   // [64,64]
    float* out = (float*)d_out;

    int npos = in_sizes[0] / DH;              // B*S

    build_skew_kernel<<<(DC * DH * DH + 255) / 256, 256>>>(L);
    liepe_expmv_kernel<<<npos, 32>>>(x, r, P, out);
}

// round 6
// speedup vs baseline: 1.2321x; 1.2321x over previous
#include <cuda_runtime.h>
#include <math.h>

#define DH 64
#define DC 3

typedef unsigned long long ull;

// Precomputed skew-symmetrized generators: 0.5*(L_k - L_k^T), [3][64][64]
__device__ float g_skew[DC * DH * DH];

__global__ void build_skew_kernel(const float* __restrict__ L) {
    int idx = blockIdx.x * blockDim.x + threadIdx.x;
    if (idx < DC * DH * DH) {
        int k   = idx / (DH * DH);
        int rem = idx - k * (DH * DH);
        int r   = rem >> 6;
        int c   = rem & 63;
        g_skew[idx] = 0.5f * (L[k * DH * DH + r * DH + c] -
                              L[k * DH * DH + c * DH + r]);
    }
}

// ---- packed f32x2 helpers ----
__device__ __forceinline__ ull pack2(float lo, float hi) {
    float2 t = make_float2(lo, hi);
    return *reinterpret_cast<ull*>(&t);
}
__device__ __forceinline__ float2 unpack2(ull v) {
    return *reinterpret_cast<float2*>(&v);
}
__device__ __forceinline__ void ffma2(ull& d, ull a, ull b) {
    asm("fma.rn.f32x2 %0, %1, %2, %0;" : "+l"(d) : "l"(a), "l"(b));
}
__device__ __forceinline__ ull mul2(ull a, ull b) {
    ull r; asm("mul.rn.f32x2 %0, %1, %2;" : "=l"(r) : "l"(a), "l"(b));
    return r;
}
__device__ __forceinline__ ull add2(ull a, ull b) {
    ull r; asm("add.rn.f32x2 %0, %1, %2;" : "=l"(r) : "l"(a), "l"(b));
    return r;
}

__device__ __forceinline__ float warp_max(float v) {
    #pragma unroll
    for (int off = 16; off >= 1; off >>= 1)
        v = fmaxf(v, __shfl_xor_sync(0xffffffffu, v, off));
    return v;
}
__device__ __forceinline__ float warp_sum(float v) {
    #pragma unroll
    for (int off = 16; off >= 1; off >>= 1)
        v += __shfl_xor_sync(0xffffffffu, v, off);
    return v;
}

// One warp (32-thread block) per (b,s) position.
// Lane l: k = l&15, h = l>>4. Owns rows 4k..4k+3 over column half [32h, 32h+32).
#define HPAD 36   // floats between half-vector bases (bank-offset the two broadcasts)

__global__ __launch_bounds__(32, 12)
void liepe_expmv_kernel(const float* __restrict__ x,
                        const float* __restrict__ rg,
                        const float* __restrict__ Psp,
                        float* __restrict__ out)
{
    __shared__ __align__(16) float sv[2][2 * HPAD];
    __shared__ float scoef[64];

    const int l = threadIdx.x;
    const int k = l & 15;
    const int h = l >> 4;
    const int pos = blockIdx.x;
    const int colbase = h * 32;
    const int physoff = h * HPAD;
    const int off4 = 4 * k + ((k >= 8) ? (HPAD - 32) : 0);

    const float r0 = __ldg(&rg[pos * DC + 0]);
    const float r1 = __ldg(&rg[pos * DC + 1]);
    const float r2 = __ldg(&rg[pos * DC + 2]);

    // ---- stage x ----
    sv[0][l]        = x[pos * DH + l];
    sv[0][HPAD + l] = x[pos * DH + 32 + l];
    __syncwarp();

    // ---- e = P_sp @ x : rows 4k..4k+3 over column half, shfl-combine ----
    float e[4];
    {
        const float4* vh = reinterpret_cast<const float4*>(&sv[0][physoff]);
        #pragma unroll
        for (int r = 0; r < 4; r++) {
            const float4* pr = reinterpret_cast<const float4*>(
                Psp + (4 * k + r) * DH + colbase);
            float d = 0.f;
            #pragma unroll
            for (int q = 0; q < 8; q++) {
                float4 pv = __ldg(&pr[q]);
                float4 vq = vh[q];
                d = fmaf(pv.x, vq.x, fmaf(pv.y, vq.y,
                    fmaf(pv.z, vq.z, fmaf(pv.w, vq.w, d))));
            }
            e[r] = d;
        }
        #pragma unroll
        for (int r = 0; r < 4; r++)
            e[r] += __shfl_xor_sync(0xffffffffu, e[r], 16);
    }
    __syncwarp();

    // ---- build A rows (4k+r, col half h), packed f32x2; F-norm + inf-norm ----
    ull A[64];                 // row r occupies A[16r .. 16r+15]
    float fs = 0.f;
    float mrow = 0.f;
    #pragma unroll
    for (int r = 0; r < 4; r++) {
        const int row = 4 * k + r;
        const float4* s0 = reinterpret_cast<const float4*>(
            g_skew + (0 * DH + row) * DH + colbase);
        const float4* s1 = reinterpret_cast<const float4*>(
            g_skew + (1 * DH + row) * DH + colbase);
        const float4* s2 = reinterpret_cast<const float4*>(
            g_skew + (2 * DH + row) * DH + colbase);
        float rs = 0.f;
        #pragma unroll
        for (int q = 0; q < 8; q++) {
            float4 v0 = __ldg(&s0[q]);
            float4 v1 = __ldg(&s1[q]);
            float4 v2 = __ldg(&s2[q]);
            float ax = fmaf(r2, v2.x, fmaf(r1, v1.x, r0 * v0.x));
            float ay = fmaf(r2, v2.y, fmaf(r1, v1.y, r0 * v0.y));
            float az = fmaf(r2, v2.z, fmaf(r1, v1.z, r0 * v0.z));
            float aw = fmaf(r2, v2.w, fmaf(r1, v1.w, r0 * v0.w));
            rs += fabsf(ax) + fabsf(ay) + fabsf(az) + fabsf(aw);
            fs = fmaf(ax, ax, fmaf(ay, ay, fmaf(az, az, fmaf(aw, aw, fs))));
            A[r * 16 + 2 * q]     = pack2(ax, ay);
            A[r * 16 + 2 * q + 1] = pack2(az, aw);
        }
        rs += __shfl_xor_sync(0xffffffffu, rs, 16);
        mrow = fmaxf(mrow, rs);
    }
    float ninf = warp_max(mrow);                 // rigorous: ||A||_2 <= ||A||_inf
    float F2   = warp_sum(fs);                   // ||A||_F^2

    // Chebyshev radius: semicircle edge ~0.25*||A||_F; 0.32 = +28% safety.
    float rho = fminf(ninf, 0.32f * sqrtf(F2));
    rho = fmaxf(rho, 0.5f);
    int kmax = (int)ceilf(rho) + 13;
    if (kmax > 50) kmax = 50;

    // scale A -> C = (2/rho) * A
    const float inv_rho = 1.0f / rho;
    {
        ull sp = pack2(2.0f * inv_rho, 2.0f * inv_rho);
        #pragma unroll
        for (int q = 0; q < 64; q++) A[q] = mul2(A[q], sp);
    }

    // ---- Bessel coefficients J_k(rho), k=0..kmax, via Miller downward ----
    {
        int K = kmax + 12;
        float jp = 0.f, jc = 1e-25f;
        float s = 0.f, c1 = 0.f, c2 = 0.f;
        for (int kk = K; kk >= 1; kk--) {
            float jm = fmaf(2.0f * (float)kk * inv_rho, jc, -jp); // j_{kk-1}
            int km1 = kk - 1;
            if (km1 == l)      c1 = jm;
            if (km1 == l + 32) c2 = jm;
            if (km1 == 0)            s += jm;
            else if ((km1 & 1) == 0) s += 2.0f * jm;
            if (fabsf(jm) > 1e24f) {
                jm *= 1e-24f; jc *= 1e-24f; s *= 1e-24f;
                c1 *= 1e-24f; c2 *= 1e-24f;
            }
            jp = jc; jc = jm;
        }
        float invs = 1.0f / s;     // J0 + 2*sum_{even>=2} J = 1 normalization
        scoef[l]      = ((l == 0) ? 1.0f : 2.0f) * c1 * invs;
        scoef[l + 32] = 2.0f * c2 * invs;
    }
    __syncwarp();

    // ---- Chebyshev: y = sum_k coef[k] * phi_k,  phi_{k+1} = C phi_k + phi_{k-1}
    float phiA[4], phiB[4], y[4];
    float cf0 = scoef[0];
    #pragma unroll
    for (int r = 0; r < 4; r++) { phiA[r] = e[r]; y[r] = cf0 * e[r]; }

    int cur = 0;
    if (h == 0)
        *reinterpret_cast<float4*>(&sv[0][off4]) =
            make_float4(e[0], e[1], e[2], e[3]);
    __syncwarp();

    // phi_1 = 0.5 * C * phi_0
    {
        const ulonglong2* vv =
            reinterpret_cast<const ulonglong2*>(&sv[0][physoff]);
        ull acc0[4] = {0ull, 0ull, 0ull, 0ull};
        ull acc1[4] = {0ull, 0ull, 0ull, 0ull};
        #pragma unroll
        for (int q = 0; q < 8; q++) {
            ulonglong2 t = vv[q];
            #pragma unroll
            for (int r = 0; r < 4; r++) {
                ffma2(acc0[r], A[r * 16 + 2 * q],     t.x);
                ffma2(acc1[r], A[r * 16 + 2 * q + 1], t.y);
            }
        }
        float cf1 = scoef[1];
        #pragma unroll
        for (int r = 0; r < 4; r++) {
            float2 f = unpack2(add2(acc0[r], acc1[r]));
            float pr = f.x + f.y;
            pr += __shfl_xor_sync(0xffffffffu, pr, 16);
            phiB[r] = 0.5f * pr;
            y[r] = fmaf(cf1, phiB[r], y[r]);
        }
        if (h == 0)
            *reinterpret_cast<float4*>(&sv[1][off4]) =
                make_float4(phiB[0], phiB[1], phiB[2], phiB[3]);
        __syncwarp();
        cur = 1;
    }

    for (int kk = 2; kk <= kmax; kk++) {
        const ulonglong2* vv =
            reinterpret_cast<const ulonglong2*>(&sv[cur][physoff]);
        ull acc0[4] = {0ull, 0ull, 0ull, 0ull};
        ull acc1[4] = {0ull, 0ull, 0ull, 0ull};
        #pragma unroll
        for (int q = 0; q < 8; q++) {
            ulonglong2 t = vv[q];
            #pragma unroll
            for (int r = 0; r < 4; r++) {
                ffma2(acc0[r], A[r * 16 + 2 * q],     t.x);
                ffma2(acc1[r], A[r * 16 + 2 * q + 1], t.y);
            }
        }
        float cf = scoef[kk];
        float pn[4];
        #pragma unroll
        for (int r = 0; r < 4; r++) {
            float2 f = unpack2(add2(acc0[r], acc1[r]));
            float pr = f.x + f.y;
            pr += __shfl_xor_sync(0xffffffffu, pr, 16);
            pn[r] = pr + phiA[r];              // phi_k = C phi_{k-1} + phi_{k-2}
            y[r] = fmaf(cf, pn[r], y[r]);
            phiA[r] = phiB[r];
            phiB[r] = pn[r];
        }
        if (kk < kmax) {
            if (h == 0)
                *reinterpret_cast<float4*>(&sv[cur ^ 1][off4]) =
                    make_float4(pn[0], pn[1], pn[2], pn[3]);
            __syncwarp();
            cur ^= 1;
        }
    }

    if (h == 0)
        *reinterpret_cast<float4*>(&out[pos * DH + 4 * k]) =
            make_float4(y[0], y[1], y[2], y[3]);
}

extern "C" void kernel_launch(void* const* d_in, const int* in_sizes, int n_in,
                              void* d_out, int out_size)
{
    const float* x = (const float*)d_in[0];   // [B,S,64]
    const float* r = (const float*)d_in[1];   // [B,S,3]
    const float* L = (const float*)d_in[2];   // [3,64,64]
    const float* P = (const float*)d_in[3];   // [64,64]
    float* out = (float*)d_out;

    int npos = in_sizes[0] / DH;              // B*S

    build_skew_kernel<<<(DC * DH * DH + 255) / 256, 256>>>(L);
    liepe_expmv_kernel<<<npos, 32>>>(x, r, P, out);
}

// round 7
// speedup vs baseline: 1.3490x; 1.0949x over previous
#include <cuda_runtime.h>
#include <math.h>

#define DH 64
#define DC 3

typedef unsigned long long ull;

// Precomputed skew-symmetrized generators: 0.5*(L_k - L_k^T), [3][64][64]
__device__ float g_skew[DC * DH * DH];
// Gram matrix of generators: [S0.S0, S0.S1, S0.S2, S1.S1, S1.S2, S2.S2]
__device__ float g_gram[6];

__global__ void build_skew_kernel(const float* __restrict__ L) {
    int idx = blockIdx.x * blockDim.x + threadIdx.x;
    if (idx < DC * DH * DH) {
        int k   = idx / (DH * DH);
        int rem = idx - k * (DH * DH);
        int r   = rem >> 6;
        int c   = rem & 63;
        g_skew[idx] = 0.5f * (L[k * DH * DH + r * DH + c] -
                              L[k * DH * DH + c * DH + r]);
    }
}

__global__ void gram_kernel() {
    __shared__ float red[8][6];
    int t = threadIdx.x;   // 256 threads
    float g[6] = {0.f, 0.f, 0.f, 0.f, 0.f, 0.f};
    for (int idx = t; idx < DH * DH; idx += 256) {
        float s0 = g_skew[idx];
        float s1 = g_skew[DH * DH + idx];
        float s2 = g_skew[2 * DH * DH + idx];
        g[0] = fmaf(s0, s0, g[0]);
        g[1] = fmaf(s0, s1, g[1]);
        g[2] = fmaf(s0, s2, g[2]);
        g[3] = fmaf(s1, s1, g[3]);
        g[4] = fmaf(s1, s2, g[4]);
        g[5] = fmaf(s2, s2, g[5]);
    }
    #pragma unroll
    for (int off = 16; off >= 1; off >>= 1)
        #pragma unroll
        for (int i = 0; i < 6; i++)
            g[i] += __shfl_xor_sync(0xffffffffu, g[i], off);
    if ((t & 31) == 0)
        #pragma unroll
        for (int i = 0; i < 6; i++) red[t >> 5][i] = g[i];
    __syncthreads();
    if (t < 6) {
        float s = 0.f;
        #pragma unroll
        for (int w = 0; w < 8; w++) s += red[w][t];
        g_gram[t] = s;
    }
}

// ---- packed f32x2 helpers ----
__device__ __forceinline__ ull pack2(float lo, float hi) {
    float2 t = make_float2(lo, hi);
    return *reinterpret_cast<ull*>(&t);
}
__device__ __forceinline__ float2 unpack2(ull v) {
    return *reinterpret_cast<float2*>(&v);
}
__device__ __forceinline__ void ffma2(ull& d, ull a, ull b) {
    asm("fma.rn.f32x2 %0, %1, %2, %0;" : "+l"(d) : "l"(a), "l"(b));
}
__device__ __forceinline__ ull add2(ull a, ull b) {
    ull r; asm("add.rn.f32x2 %0, %1, %2;" : "=l"(r) : "l"(a), "l"(b));
    return r;
}

// One warp (32-thread block) per (b,s) position.
// Lane l: k = l&15, h = l>>4. Owns rows 4k..4k+3 over column half [32h, 32h+32).
#define HPAD 36   // floats between half-vector bases (bank-offset the two broadcasts)

__global__ __launch_bounds__(32, 12)
void liepe_expmv_kernel(const float* __restrict__ x,
                        const float* __restrict__ rg,
                        const float* __restrict__ Psp,
                        float* __restrict__ out)
{
    __shared__ __align__(16) float sv[3][2 * HPAD];
    __shared__ float scoef[64];

    const int l = threadIdx.x;
    const int k = l & 15;
    const int h = l >> 4;
    const int pos = blockIdx.x;
    const int colbase = h * 32;
    const int physoff = h * HPAD;
    const int off4 = 4 * k + ((k >= 8) ? (HPAD - 32) : 0);

    const float r0 = __ldg(&rg[pos * DC + 0]);
    const float r1 = __ldg(&rg[pos * DC + 1]);
    const float r2 = __ldg(&rg[pos * DC + 2]);

    // ---- rho from generator Gram matrix: ||A||_F^2 = r' G r ----
    float rho;
    {
        float g0 = __ldg(&g_gram[0]), g1 = __ldg(&g_gram[1]);
        float g2 = __ldg(&g_gram[2]), g3 = __ldg(&g_gram[3]);
        float g4 = __ldg(&g_gram[4]), g5 = __ldg(&g_gram[5]);
        float F2 = r0 * r0 * g0 + r1 * r1 * g3 + r2 * r2 * g5
                 + 2.0f * (r0 * r1 * g1 + r0 * r2 * g2 + r1 * r2 * g4);
        // spectral edge ~0.25*||A||_F for n=64; 0.335 = +34% safety
        rho = 0.335f * sqrtf(fmaxf(F2, 0.f));
        rho = fmaxf(rho, 0.5f);
    }
    int kmax = (int)ceilf(rho) + 11;
    if (kmax > 48) kmax = 48;
    const float inv_rho = 1.0f / rho;

    // ---- Bessel coefficients J_k(rho) via Miller downward (A not yet live) ----
    {
        int K = kmax + 10;
        float jp = 0.f, jc = 1e-25f;
        float s = 0.f, c1 = 0.f, c2 = 0.f;
        for (int kk = K; kk >= 1; kk--) {
            float jm = fmaf(2.0f * (float)kk * inv_rho, jc, -jp); // J_{kk-1}
            int km1 = kk - 1;
            if (km1 == l)      c1 = jm;
            if (km1 == l + 32) c2 = jm;
            if (km1 == 0)            s += jm;
            else if ((km1 & 1) == 0) s += 2.0f * jm;
            if (fabsf(jm) > 1e24f) {
                jm *= 1e-24f; jc *= 1e-24f; s *= 1e-24f;
                c1 *= 1e-24f; c2 *= 1e-24f;
            }
            jp = jc; jc = jm;
        }
        float invs = 1.0f / s;     // J0 + 2*sum_{even>=2} J_k = 1
        scoef[l]      = ((l == 0) ? 1.0f : 2.0f) * c1 * invs;
        scoef[l + 32] = 2.0f * c2 * invs;
    }

    // ---- stage x ----
    sv[0][l]        = x[pos * DH + l];
    sv[0][HPAD + l] = x[pos * DH + 32 + l];
    __syncwarp();

    // ---- e = P_sp @ x ----
    float e[4];
    {
        const float4* vh = reinterpret_cast<const float4*>(&sv[0][physoff]);
        #pragma unroll
        for (int r = 0; r < 4; r++) {
            const float4* pr = reinterpret_cast<const float4*>(
                Psp + (4 * k + r) * DH + colbase);
            float d = 0.f;
            #pragma unroll
            for (int q = 0; q < 8; q++) {
                float4 pv = __ldg(&pr[q]);
                float4 vq = vh[q];
                d = fmaf(pv.x, vq.x, fmaf(pv.y, vq.y,
                    fmaf(pv.z, vq.z, fmaf(pv.w, vq.w, d))));
            }
            e[r] = d;
        }
        #pragma unroll
        for (int r = 0; r < 4; r++)
            e[r] += __shfl_xor_sync(0xffffffffu, e[r], 16);
    }
    __syncwarp();
    // phi0 := e (overwrite x; safe after syncwarp)
    if (h == 0)
        *reinterpret_cast<float4*>(&sv[0][off4]) =
            make_float4(e[0], e[1], e[2], e[3]);
    __syncwarp();

    // ---- build C = (2/rho)*A rows directly (scale folded into coefs) ----
    ull A[64];                 // row r occupies A[16r .. 16r+15]
    {
        const float cs = 2.0f * inv_rho;
        const float c0 = r0 * cs, c1f = r1 * cs, c2f = r2 * cs;
        #pragma unroll
        for (int r = 0; r < 4; r++) {
            const int row = 4 * k + r;
            const float4* s0 = reinterpret_cast<const float4*>(
                g_skew + (0 * DH + row) * DH + colbase);
            const float4* s1 = reinterpret_cast<const float4*>(
                g_skew + (1 * DH + row) * DH + colbase);
            const float4* s2 = reinterpret_cast<const float4*>(
                g_skew + (2 * DH + row) * DH + colbase);
            #pragma unroll
            for (int q = 0; q < 8; q++) {
                float4 v0 = __ldg(&s0[q]);
                float4 v1 = __ldg(&s1[q]);
                float4 v2 = __ldg(&s2[q]);
                float ax = fmaf(c2f, v2.x, fmaf(c1f, v1.x, c0 * v0.x));
                float ay = fmaf(c2f, v2.y, fmaf(c1f, v1.y, c0 * v0.y));
                float az = fmaf(c2f, v2.z, fmaf(c1f, v1.z, c0 * v0.z));
                float aw = fmaf(c2f, v2.w, fmaf(c1f, v1.w, c0 * v0.w));
                A[r * 16 + 2 * q]     = pack2(ax, ay);
                A[r * 16 + 2 * q + 1] = pack2(az, aw);
            }
        }
    }

    // ---- y = coef0*phi0; phi1 = 0.5*C*phi0 -> sv[1] ----
    float y[4];
    {
        float cf0 = scoef[0];
        #pragma unroll
        for (int r = 0; r < 4; r++) y[r] = cf0 * e[r];

        const ulonglong2* vv =
            reinterpret_cast<const ulonglong2*>(&sv[0][physoff]);
        ull acc0[4] = {0ull, 0ull, 0ull, 0ull};
        ull acc1[4] = {0ull, 0ull, 0ull, 0ull};
        #pragma unroll
        for (int q = 0; q < 8; q++) {
            ulonglong2 t = vv[q];
            #pragma unroll
            for (int r = 0; r < 4; r++) {
                ffma2(acc0[r], A[r * 16 + 2 * q],     t.x);
                ffma2(acc1[r], A[r * 16 + 2 * q + 1], t.y);
            }
        }
        float cf1 = scoef[1];
        float p1[4];
        #pragma unroll
        for (int r = 0; r < 4; r++) {
            float2 f = unpack2(add2(acc0[r], acc1[r]));
            float pr = f.x + f.y;
            pr += __shfl_xor_sync(0xffffffffu, pr, 16);
            p1[r] = 0.5f * pr;
            y[r] = fmaf(cf1, p1[r], y[r]);
        }
        if (h == 0)
            *reinterpret_cast<float4*>(&sv[1][off4]) =
                make_float4(p1[0], p1[1], p1[2], p1[3]);
        __syncwarp();
    }

    // ---- Chebyshev loop: phi_k = C*phi_{k-1} + phi_{k-2} (phi_{k-2} in smem) ----
    int b1 = 1, b2 = 0, bf = 2;   // sv[b1]=phi_{k-1}, sv[b2]=phi_{k-2}, sv[bf]=free
    for (int kk = 2; kk <= kmax; kk++) {
        float4 old4 = *reinterpret_cast<const float4*>(&sv[b2][off4]);
        const ulonglong2* vv =
            reinterpret_cast<const ulonglong2*>(&sv[b1][physoff]);
        ull acc0[4] = {0ull, 0ull, 0ull, 0ull};
        ull acc1[4] = {0ull, 0ull, 0ull, 0ull};
        #pragma unroll
        for (int q = 0; q < 8; q++) {
            ulonglong2 t = vv[q];
            #pragma unroll
            for (int r = 0; r < 4; r++) {
                ffma2(acc0[r], A[r * 16 + 2 * q],     t.x);
                ffma2(acc1[r], A[r * 16 + 2 * q + 1], t.y);
            }
        }
        float cf = scoef[kk];
        float pn[4];
        const float old_[4] = {old4.x, old4.y, old4.z, old4.w};
        #pragma unroll
        for (int r = 0; r < 4; r++) {
            float2 f = unpack2(add2(acc0[r], acc1[r]));
            float pr = f.x + f.y;
            pr += __shfl_xor_sync(0xffffffffu, pr, 16);
            pn[r] = pr + old_[r];
            y[r] = fmaf(cf, pn[r], y[r]);
        }
        if (kk < kmax) {
            if (h == 0)
                *reinterpret_cast<float4*>(&sv[bf][off4]) =
                    make_float4(pn[0], pn[1], pn[2], pn[3]);
            __syncwarp();
            int tmp = b2; b2 = b1; b1 = bf; bf = tmp;
        }
    }

    if (h == 0)
        *reinterpret_cast<float4*>(&out[pos * DH + 4 * k]) =
            make_float4(y[0], y[1], y[2], y[3]);
}

extern "C" void kernel_launch(void* const* d_in, const int* in_sizes, int n_in,
                              void* d_out, int out_size)
{
    const float* x = (const float*)d_in[0];   // [B,S,64]
    const float* r = (const float*)d_in[1];   // [B,S,3]
    const float* L = (const float*)d_in[2];   // [3,64,64]
    const float* P = (const float*)d_in[3];   // [64,64]
    float* out = (float*)d_out;

    int npos = in_sizes[0] / DH;              // B*S

    build_skew_kernel<<<(DC * DH * DH + 255) / 256, 256>>>(L);
    gram_kernel<<<1, 256>>>();
    liepe_expmv_kernel<<<npos, 32>>>(x, r, P, out);
}

// round 8
// speedup vs baseline: 1.5787x; 1.1702x over previous
#include <cuda_runtime.h>
#include <math.h>

#define DH 64
#define DC 3

typedef unsigned long long ull;

// Precomputed skew-symmetrized generators: 0.5*(L_k - L_k^T), [3][64][64]
__device__ float g_skew[DC * DH * DH];
// Gram matrix of generators: [S0.S0, S0.S1, S0.S2, S1.S1, S1.S2, S2.S2]
__device__ float g_gram[6];

__global__ void build_skew_kernel(const float* __restrict__ L) {
    int idx = blockIdx.x * blockDim.x + threadIdx.x;
    if (idx < DC * DH * DH) {
        int k   = idx / (DH * DH);
        int rem = idx - k * (DH * DH);
        int r   = rem >> 6;
        int c   = rem & 63;
        g_skew[idx] = 0.5f * (L[k * DH * DH + r * DH + c] -
                              L[k * DH * DH + c * DH + r]);
    }
}

__global__ void gram_kernel() {
    __shared__ float red[8][6];
    int t = threadIdx.x;   // 256 threads
    float g[6] = {0.f, 0.f, 0.f, 0.f, 0.f, 0.f};
    for (int idx = t; idx < DH * DH; idx += 256) {
        float s0 = g_skew[idx];
        float s1 = g_skew[DH * DH + idx];
        float s2 = g_skew[2 * DH * DH + idx];
        g[0] = fmaf(s0, s0, g[0]);
        g[1] = fmaf(s0, s1, g[1]);
        g[2] = fmaf(s0, s2, g[2]);
        g[3] = fmaf(s1, s1, g[3]);
        g[4] = fmaf(s1, s2, g[4]);
        g[5] = fmaf(s2, s2, g[5]);
    }
    #pragma unroll
    for (int off = 16; off >= 1; off >>= 1)
        #pragma unroll
        for (int i = 0; i < 6; i++)
            g[i] += __shfl_xor_sync(0xffffffffu, g[i], off);
    if ((t & 31) == 0)
        #pragma unroll
        for (int i = 0; i < 6; i++) red[t >> 5][i] = g[i];
    __syncthreads();
    if (t < 6) {
        float s = 0.f;
        #pragma unroll
        for (int w = 0; w < 8; w++) s += red[w][t];
        g_gram[t] = s;
    }
}

// ---- packed f32x2 helpers ----
__device__ __forceinline__ ull pack2(float lo, float hi) {
    float2 t = make_float2(lo, hi);
    return *reinterpret_cast<ull*>(&t);
}
__device__ __forceinline__ float2 unpack2(ull v) {
    return *reinterpret_cast<float2*>(&v);
}
__device__ __forceinline__ void ffma2(ull& d, ull a, ull b) {
    asm("fma.rn.f32x2 %0, %1, %2, %0;" : "+l"(d) : "l"(a), "l"(b));
}
__device__ __forceinline__ ull add2(ull a, ull b) {
    ull r; asm("add.rn.f32x2 %0, %1, %2;" : "=l"(r) : "l"(a), "l"(b));
    return r;
}

// One warp (32-thread block) per (b,s) position.
// Lane l: k = l&15, h = l>>4. Owns rows 4k..4k+3 over column half [32h, 32h+32).
#define HPAD 36   // floats between half-vector bases (bank-offset the two broadcasts)

// One Chebyshev term with COMPILE-TIME buffer indices.
// sv[B1]=phi_{k-1}, sv[B2]=phi_{k-2}, sv[BF]=destination for phi_k.
template <int B1, int B2, int BF>
__device__ __forceinline__ void cheb_iter(
    float (*sv)[2 * HPAD], const ull* A, const float* scoef,
    float* y, int kk, int kmax, int h, int off4, int physoff)
{
    float4 old4 = *reinterpret_cast<const float4*>(&sv[B2][off4]);
    const ulonglong2* vv =
        reinterpret_cast<const ulonglong2*>(&sv[B1][physoff]);
    ull acc0[4] = {0ull, 0ull, 0ull, 0ull};
    ull acc1[4] = {0ull, 0ull, 0ull, 0ull};
    #pragma unroll
    for (int q = 0; q < 8; q++) {
        ulonglong2 t = vv[q];
        #pragma unroll
        for (int r = 0; r < 4; r++) {
            ffma2(acc0[r], A[r * 16 + 2 * q],     t.x);
            ffma2(acc1[r], A[r * 16 + 2 * q + 1], t.y);
        }
    }
    float cf = scoef[kk];
    float pn[4];
    const float old_[4] = {old4.x, old4.y, old4.z, old4.w};
    #pragma unroll
    for (int r = 0; r < 4; r++) {
        float2 f = unpack2(add2(acc0[r], acc1[r]));
        float pr = f.x + f.y;
        pr += __shfl_xor_sync(0xffffffffu, pr, 16);
        pn[r] = pr + old_[r];
        y[r] = fmaf(cf, pn[r], y[r]);
    }
    if (kk < kmax) {
        if (h == 0)
            *reinterpret_cast<float4*>(&sv[BF][off4]) =
                make_float4(pn[0], pn[1], pn[2], pn[3]);
        __syncwarp();
    }
}

__global__ __launch_bounds__(32, 11)
void liepe_expmv_kernel(const float* __restrict__ x,
                        const float* __restrict__ rg,
                        const float* __restrict__ Psp,
                        float* __restrict__ out)
{
    __shared__ __align__(16) float sv[3][2 * HPAD];
    __shared__ float scoef[64];

    const int l = threadIdx.x;
    const int k = l & 15;
    const int h = l >> 4;
    const int pos = blockIdx.x;
    const int colbase = h * 32;
    const int physoff = h * HPAD;
    const int off4 = 4 * k + ((k >= 8) ? (HPAD - 32) : 0);

    const float r0 = __ldg(&rg[pos * DC + 0]);
    const float r1 = __ldg(&rg[pos * DC + 1]);
    const float r2 = __ldg(&rg[pos * DC + 2]);

    // ---- rho from generator Gram matrix: ||A||_F^2 = r' G r ----
    float rho;
    {
        float g0 = __ldg(&g_gram[0]), g1 = __ldg(&g_gram[1]);
        float g2 = __ldg(&g_gram[2]), g3 = __ldg(&g_gram[3]);
        float g4 = __ldg(&g_gram[4]), g5 = __ldg(&g_gram[5]);
        float F2 = r0 * r0 * g0 + r1 * r1 * g3 + r2 * r2 * g5
                 + 2.0f * (r0 * r1 * g1 + r0 * r2 * g2 + r1 * r2 * g4);
        // spectral edge ~0.25*||A||_F for n=64; 0.335 = +34% safety
        rho = 0.335f * sqrtf(fmaxf(F2, 0.f));
        rho = fmaxf(rho, 0.5f);
    }
    int kmax = (int)ceilf(rho) + 10;
    if (kmax > 48) kmax = 48;
    const float inv_rho = 1.0f / rho;

    // ---- Bessel coefficients J_k(rho) via Miller downward (A not yet live) ----
    {
        int K = kmax + 10;
        float jp = 0.f, jc = 1e-25f;
        float s = 0.f, c1 = 0.f, c2 = 0.f;
        for (int kk = K; kk >= 1; kk--) {
            float jm = fmaf(2.0f * (float)kk * inv_rho, jc, -jp); // J_{kk-1}
            int km1 = kk - 1;
            if (km1 == l)      c1 = jm;
            if (km1 == l + 32) c2 = jm;
            if (km1 == 0)            s += jm;
            else if ((km1 & 1) == 0) s += 2.0f * jm;
            if (fabsf(jm) > 1e24f) {
                jm *= 1e-24f; jc *= 1e-24f; s *= 1e-24f;
                c1 *= 1e-24f; c2 *= 1e-24f;
            }
            jp = jc; jc = jm;
        }
        float invs = 1.0f / s;     // J0 + 2*sum_{even>=2} J_k = 1
        scoef[l]      = ((l == 0) ? 1.0f : 2.0f) * c1 * invs;
        scoef[l + 32] = 2.0f * c2 * invs;
    }

    // ---- stage x ----
    sv[0][l]        = x[pos * DH + l];
    sv[0][HPAD + l] = x[pos * DH + 32 + l];
    __syncwarp();

    // ---- e = P_sp @ x ----
    float e[4];
    {
        const float4* vh = reinterpret_cast<const float4*>(&sv[0][physoff]);
        #pragma unroll
        for (int r = 0; r < 4; r++) {
            const float4* pr = reinterpret_cast<const float4*>(
                Psp + (4 * k + r) * DH + colbase);
            float d = 0.f;
            #pragma unroll
            for (int q = 0; q < 8; q++) {
                float4 pv = __ldg(&pr[q]);
                float4 vq = vh[q];
                d = fmaf(pv.x, vq.x, fmaf(pv.y, vq.y,
                    fmaf(pv.z, vq.z, fmaf(pv.w, vq.w, d))));
            }
            e[r] = d;
        }
        #pragma unroll
        for (int r = 0; r < 4; r++)
            e[r] += __shfl_xor_sync(0xffffffffu, e[r], 16);
    }
    __syncwarp();
    // phi0 := e (overwrite x; safe after syncwarp)
    if (h == 0)
        *reinterpret_cast<float4*>(&sv[0][off4]) =
            make_float4(e[0], e[1], e[2], e[3]);
    __syncwarp();

    // ---- build C = (2/rho)*A rows directly (scale folded into coefs) ----
    ull A[64];                 // row r occupies A[16r .. 16r+15]
    {
        const float cs = 2.0f * inv_rho;
        const float c0 = r0 * cs, c1f = r1 * cs, c2f = r2 * cs;
        #pragma unroll
        for (int r = 0; r < 4; r++) {
            const int row = 4 * k + r;
            const float4* s0 = reinterpret_cast<const float4*>(
                g_skew + (0 * DH + row) * DH + colbase);
            const float4* s1 = reinterpret_cast<const float4*>(
                g_skew + (1 * DH + row) * DH + colbase);
            const float4* s2 = reinterpret_cast<const float4*>(
                g_skew + (2 * DH + row) * DH + colbase);
            #pragma unroll
            for (int q = 0; q < 8; q++) {
                float4 v0 = __ldg(&s0[q]);
                float4 v1 = __ldg(&s1[q]);
                float4 v2 = __ldg(&s2[q]);
                float ax = fmaf(c2f, v2.x, fmaf(c1f, v1.x, c0 * v0.x));
                float ay = fmaf(c2f, v2.y, fmaf(c1f, v1.y, c0 * v0.y));
                float az = fmaf(c2f, v2.z, fmaf(c1f, v1.z, c0 * v0.z));
                float aw = fmaf(c2f, v2.w, fmaf(c1f, v1.w, c0 * v0.w));
                A[r * 16 + 2 * q]     = pack2(ax, ay);
                A[r * 16 + 2 * q + 1] = pack2(az, aw);
            }
        }
    }

    // ---- y = coef0*phi0; phi1 = 0.5*C*phi0 -> sv[1] ----
    float y[4];
    {
        float cf0 = scoef[0];
        #pragma unroll
        for (int r = 0; r < 4; r++) y[r] = cf0 * e[r];

        const ulonglong2* vv =
            reinterpret_cast<const ulonglong2*>(&sv[0][physoff]);
        ull acc0[4] = {0ull, 0ull, 0ull, 0ull};
        ull acc1[4] = {0ull, 0ull, 0ull, 0ull};
        #pragma unroll
        for (int q = 0; q < 8; q++) {
            ulonglong2 t = vv[q];
            #pragma unroll
            for (int r = 0; r < 4; r++) {
                ffma2(acc0[r], A[r * 16 + 2 * q],     t.x);
                ffma2(acc1[r], A[r * 16 + 2 * q + 1], t.y);
            }
        }
        float cf1 = scoef[1];
        float p1[4];
        #pragma unroll
        for (int r = 0; r < 4; r++) {
            float2 f = unpack2(add2(acc0[r], acc1[r]));
            float pr = f.x + f.y;
            pr += __shfl_xor_sync(0xffffffffu, pr, 16);
            p1[r] = 0.5f * pr;
            y[r] = fmaf(cf1, p1[r], y[r]);
        }
        if (h == 0)
            *reinterpret_cast<float4*>(&sv[1][off4]) =
                make_float4(p1[0], p1[1], p1[2], p1[3]);
        __syncwarp();
    }

    // ---- Chebyshev loop, unrolled by 3 with constant buffer indices ----
    // Rotation: (b1,b2,bf) = (1,0,2) -> (2,1,0) -> (0,2,1) -> repeat.
    {
        int kk = 2;
        while (kk <= kmax) {
            cheb_iter<1, 0, 2>(sv, A, scoef, y, kk, kmax, h, off4, physoff);
            if (++kk > kmax) break;
            cheb_iter<2, 1, 0>(sv, A, scoef, y, kk, kmax, h, off4, physoff);
            if (++kk > kmax) break;
            cheb_iter<0, 2, 1>(sv, A, scoef, y, kk, kmax, h, off4, physoff);
            ++kk;
        }
    }

    if (h == 0)
        *reinterpret_cast<float4*>(&out[pos * DH + 4 * k]) =
            make_float4(y[0], y[1], y[2], y[3]);
}

extern "C" void kernel_launch(void* const* d_in, const int* in_sizes, int n_in,
                              void* d_out, int out_size)
{
    const float* x = (const float*)d_in[0];   // [B,S,64]
    const float* r = (const float*)d_in[1];   // [B,S,3]
    const float* L = (const float*)d_in[2];   // [3,64,64]
    const float* P = (const float*)d_in[3];   // [64,64]
    float* out = (float*)d_out;

    int npos = in_sizes[0] / DH;              // B*S

    build_skew_kernel<<<(DC * DH * DH + 255) / 256, 256>>>(L);
    gram_kernel<<<1, 256>>>();
    liepe_expmv_kernel<<<npos, 32>>>(x, r, P, out);
}

// round 9
// speedup vs baseline: 1.6225x; 1.0278x over previous
#include <cuda_runtime.h>
#include <math.h>

#define DH 64
#define DC 3

typedef unsigned long long ull;

// Precomputed skew-symmetrized generators: 0.5*(L_k - L_k^T), [3][64][64]
__device__ float g_skew[DC * DH * DH];
// Gram matrix of generators: [S0.S0, S0.S1, S0.S2, S1.S1, S1.S2, S2.S2]
__device__ float g_gram[6];

__global__ void build_skew_kernel(const float* __restrict__ L) {
    int idx = blockIdx.x * blockDim.x + threadIdx.x;
    if (idx < DC * DH * DH) {
        int k   = idx / (DH * DH);
        int rem = idx - k * (DH * DH);
        int r   = rem >> 6;
        int c   = rem & 63;
        g_skew[idx] = 0.5f * (L[k * DH * DH + r * DH + c] -
                              L[k * DH * DH + c * DH + r]);
    }
}

__global__ void gram_kernel() {
    __shared__ float red[8][6];
    int t = threadIdx.x;   // 256 threads
    float g[6] = {0.f, 0.f, 0.f, 0.f, 0.f, 0.f};
    for (int idx = t; idx < DH * DH; idx += 256) {
        float s0 = g_skew[idx];
        float s1 = g_skew[DH * DH + idx];
        float s2 = g_skew[2 * DH * DH + idx];
        g[0] = fmaf(s0, s0, g[0]);
        g[1] = fmaf(s0, s1, g[1]);
        g[2] = fmaf(s0, s2, g[2]);
        g[3] = fmaf(s1, s1, g[3]);
        g[4] = fmaf(s1, s2, g[4]);
        g[5] = fmaf(s2, s2, g[5]);
    }
    #pragma unroll
    for (int off = 16; off >= 1; off >>= 1)
        #pragma unroll
        for (int i = 0; i < 6; i++)
            g[i] += __shfl_xor_sync(0xffffffffu, g[i], off);
    if ((t & 31) == 0)
        #pragma unroll
        for (int i = 0; i < 6; i++) red[t >> 5][i] = g[i];
    __syncthreads();
    if (t < 6) {
        float s = 0.f;
        #pragma unroll
        for (int w = 0; w < 8; w++) s += red[w][t];
        g_gram[t] = s;
    }
}

// ---- packed f32x2 helpers ----
__device__ __forceinline__ ull pack2(float lo, float hi) {
    float2 t = make_float2(lo, hi);
    return *reinterpret_cast<ull*>(&t);
}
__device__ __forceinline__ float2 unpack2(ull v) {
    return *reinterpret_cast<float2*>(&v);
}
__device__ __forceinline__ void ffma2(ull& d, ull a, ull b) {
    asm("fma.rn.f32x2 %0, %1, %2, %0;" : "+l"(d) : "l"(a), "l"(b));
}
__device__ __forceinline__ ull add2(ull a, ull b) {
    ull r; asm("add.rn.f32x2 %0, %1, %2;" : "=l"(r) : "l"(a), "l"(b));
    return r;
}

// Full-row matvec: lane owns rows l and l+32 over all 64 columns.
// A0 = row l (32 x f32x2), A1 = row l+32. v read broadcast from smem.
// 8 accumulator chains of depth 8; no shuffles.
__device__ __forceinline__ void matvec_fr(const ull* A0, const ull* A1,
                                          const float* v,
                                          float& o0, float& o1)
{
    const ulonglong2* vv = reinterpret_cast<const ulonglong2*>(v);
    ull a0[4] = {0ull, 0ull, 0ull, 0ull};
    ull a1[4] = {0ull, 0ull, 0ull, 0ull};
    #pragma unroll
    for (int q = 0; q < 16; q++) {
        ulonglong2 t = vv[q];        // (v[4q],v[4q+1]), (v[4q+2],v[4q+3])
        ffma2(a0[(2 * q)     & 3], A0[2 * q],     t.x);
        ffma2(a0[(2 * q + 1) & 3], A0[2 * q + 1], t.y);
        ffma2(a1[(2 * q)     & 3], A1[2 * q],     t.x);
        ffma2(a1[(2 * q + 1) & 3], A1[2 * q + 1], t.y);
    }
    float2 f0 = unpack2(add2(add2(a0[0], a0[1]), add2(a0[2], a0[3])));
    o0 = f0.x + f0.y;
    float2 f1 = unpack2(add2(add2(a1[0], a1[1]), add2(a1[2], a1[3])));
    o1 = f1.x + f1.y;
}

// One Chebyshev term with COMPILE-TIME buffer indices.
// sv[B1]=phi_{k-1}, sv[B2]=phi_{k-2}, sv[BF]=destination for phi_k.
template <int B1, int B2, int BF>
__device__ __forceinline__ void cheb_iter(
    float (*sv)[DH], const ull* A0, const ull* A1, const float* scoef,
    float& y0, float& y1, int kk, int l)
{
    float old0 = sv[B2][l];
    float old1 = sv[B2][l + 32];
    float o0, o1;
    matvec_fr(A0, A1, sv[B1], o0, o1);
    float cf = scoef[kk];
    float pn0 = o0 + old0;
    float pn1 = o1 + old1;
    y0 = fmaf(cf, pn0, y0);
    y1 = fmaf(cf, pn1, y1);
    sv[BF][l]      = pn0;    // uniform store, no divergence
    sv[BF][l + 32] = pn1;
    __syncwarp();
}

__global__ __launch_bounds__(32, 11)
void liepe_expmv_kernel(const float* __restrict__ x,
                        const float* __restrict__ rg,
                        const float* __restrict__ Psp,
                        float* __restrict__ out)
{
    __shared__ __align__(16) float sv[3][DH];
    __shared__ float scoef[64];

    const int l = threadIdx.x;
    const int pos = blockIdx.x;

    const float r0 = __ldg(&rg[pos * DC + 0]);
    const float r1 = __ldg(&rg[pos * DC + 1]);
    const float r2 = __ldg(&rg[pos * DC + 2]);

    // ---- rho from generator Gram matrix: ||A||_F^2 = r' G r ----
    float rho;
    {
        float g0 = __ldg(&g_gram[0]), g1 = __ldg(&g_gram[1]);
        float g2 = __ldg(&g_gram[2]), g3 = __ldg(&g_gram[3]);
        float g4 = __ldg(&g_gram[4]), g5 = __ldg(&g_gram[5]);
        float F2 = r0 * r0 * g0 + r1 * r1 * g3 + r2 * r2 * g5
                 + 2.0f * (r0 * r1 * g1 + r0 * r2 * g2 + r1 * r2 * g4);
        // spectral edge ~0.25*||A||_F for n=64; 0.335 = +34% safety
        rho = 0.335f * sqrtf(fmaxf(F2, 0.f));
        rho = fmaxf(rho, 0.5f);
    }
    int kmax = (int)ceilf(rho) + 9;
    if (kmax > 48) kmax = 48;
    const float inv_rho = 1.0f / rho;

    // ---- Bessel coefficients J_k(rho) via Miller downward (A not yet live) ----
    {
        int K = kmax + 10;
        float jp = 0.f, jc = 1e-25f;
        float s = 0.f, c1 = 0.f, c2 = 0.f;
        for (int kk = K; kk >= 1; kk--) {
            float jm = fmaf(2.0f * (float)kk * inv_rho, jc, -jp); // J_{kk-1}
            int km1 = kk - 1;
            if (km1 == l)      c1 = jm;
            if (km1 == l + 32) c2 = jm;
            if (km1 == 0)            s += jm;
            else if ((km1 & 1) == 0) s += 2.0f * jm;
            if (fabsf(jm) > 1e24f) {
                jm *= 1e-24f; jc *= 1e-24f; s *= 1e-24f;
                c1 *= 1e-24f; c2 *= 1e-24f;
            }
            jp = jc; jc = jm;
        }
        float invs = 1.0f / s;     // J0 + 2*sum_{even>=2} J_k = 1
        scoef[l]      = ((l == 0) ? 1.0f : 2.0f) * c1 * invs;
        scoef[l + 32] = 2.0f * c2 * invs;
    }

    // ---- stage x ----
    sv[0][l]      = x[pos * DH + l];
    sv[0][l + 32] = x[pos * DH + 32 + l];
    __syncwarp();

    // ---- e = P_sp @ x : rows l and l+32, broadcast reads, no shuffles ----
    float e0, e1;
    {
        const float4* vq4 = reinterpret_cast<const float4*>(sv[0]);
        const float4* pr0 = reinterpret_cast<const float4*>(Psp + l * DH);
        const float4* pr1 = reinterpret_cast<const float4*>(Psp + (l + 32) * DH);
        float d0 = 0.f, d1 = 0.f;
        #pragma unroll
        for (int q = 0; q < 16; q++) {
            float4 vq = vq4[q];
            float4 p0 = __ldg(&pr0[q]);
            float4 p1 = __ldg(&pr1[q]);
            d0 = fmaf(p0.x, vq.x, fmaf(p0.y, vq.y,
                 fmaf(p0.z, vq.z, fmaf(p0.w, vq.w, d0))));
            d1 = fmaf(p1.x, vq.x, fmaf(p1.y, vq.y,
                 fmaf(p1.z, vq.z, fmaf(p1.w, vq.w, d1))));
        }
        e0 = d0; e1 = d1;
    }
    __syncwarp();
    // phi0 := e (overwrite x staging; safe after syncwarp)
    sv[0][l]      = e0;
    sv[0][l + 32] = e1;
    __syncwarp();

    // ---- build C = (2/rho)*A rows l and l+32 (scale folded in) ----
    ull A0[32], A1[32];
    {
        const float cs = 2.0f * inv_rho;
        const float c0 = r0 * cs, c1f = r1 * cs, c2f = r2 * cs;
        #pragma unroll
        for (int rr = 0; rr < 2; rr++) {
            const int row = l + rr * 32;
            ull* Ad = rr ? A1 : A0;
            const float4* s0 = reinterpret_cast<const float4*>(
                g_skew + (0 * DH + row) * DH);
            const float4* s1 = reinterpret_cast<const float4*>(
                g_skew + (1 * DH + row) * DH);
            const float4* s2 = reinterpret_cast<const float4*>(
                g_skew + (2 * DH + row) * DH);
            #pragma unroll
            for (int q = 0; q < 16; q++) {
                float4 v0 = __ldg(&s0[q]);
                float4 v1 = __ldg(&s1[q]);
                float4 v2 = __ldg(&s2[q]);
                float ax = fmaf(c2f, v2.x, fmaf(c1f, v1.x, c0 * v0.x));
                float ay = fmaf(c2f, v2.y, fmaf(c1f, v1.y, c0 * v0.y));
                float az = fmaf(c2f, v2.z, fmaf(c1f, v1.z, c0 * v0.z));
                float aw = fmaf(c2f, v2.w, fmaf(c1f, v1.w, c0 * v0.w));
                Ad[2 * q]     = pack2(ax, ay);
                Ad[2 * q + 1] = pack2(az, aw);
            }
        }
    }

    // ---- y = coef0*phi0; phi1 = 0.5*C*phi0 -> sv[1] ----
    float cf0 = scoef[0];
    float y0 = cf0 * e0, y1 = cf0 * e1;
    {
        float o0, o1;
        matvec_fr(A0, A1, sv[0], o0, o1);
        float cf1 = scoef[1];
        float p10 = 0.5f * o0;
        float p11 = 0.5f * o1;
        y0 = fmaf(cf1, p10, y0);
        y1 = fmaf(cf1, p11, y1);
        sv[1][l]      = p10;
        sv[1][l + 32] = p11;
        __syncwarp();
    }

    // ---- Chebyshev loop, unrolled by 3 with constant buffer indices ----
    // Rotation: (b1,b2,bf) = (1,0,2) -> (2,1,0) -> (0,2,1) -> repeat.
    {
        int kk = 2;
        while (kk <= kmax) {
            cheb_iter<1, 0, 2>(sv, A0, A1, scoef, y0, y1, kk, l);
            if (++kk > kmax) break;
            cheb_iter<2, 1, 0>(sv, A0, A1, scoef, y0, y1, kk, l);
            if (++kk > kmax) break;
            cheb_iter<0, 2, 1>(sv, A0, A1, scoef, y0, y1, kk, l);
            ++kk;
        }
    }

    out[pos * DH + l]      = y0;
    out[pos * DH + l + 32] = y1;
}

extern "C" void kernel_launch(void* const* d_in, const int* in_sizes, int n_in,
                              void* d_out, int out_size)
{
    const float* x = (const float*)d_in[0];   // [B,S,64]
    const float* r = (const float*)d_in[1];   // [B,S,3]
    const float* L = (const float*)d_in[2];   // [3,64,64]
    const float* P = (const float*)d_in[3];   // [64,64]
    float* out = (float*)d_out;

    int npos = in_sizes[0] / DH;              // B*S

    build_skew_kernel<<<(DC * DH * DH + 255) / 256, 256>>>(L);
    gram_kernel<<<1, 256>>>();
    liepe_expmv_kernel<<<npos, 32>>>(x, r, P, out);
}

// round 10
// speedup vs baseline: 4.3190x; 2.6619x over previous
#include <cuda_runtime.h>
#include <math.h>

#define DH 64
#define DC 3

typedef unsigned long long ull;

// Lane-interleaved generators: float4 index ((gen*2+rr)*16+q)*32 + l holds
// S_gen[row = l+32*rr][cols 4q..4q+3], S = 0.5*(L - L^T).  3*2*16*32 float4s.
__device__ float4 g_skew_il[DC * 2 * 16 * 32];
// Lane-interleaved P_sp: float4 index (rr*16+q)*32 + l holds
// Psp[row = l+32*rr][cols 4q..4q+3].
__device__ float4 g_psp_il[2 * 16 * 32];
// Gram matrix of generators: [S0.S0, S0.S1, S0.S2, S1.S1, S1.S2, S2.S2]
__device__ float g_gram[6];

__global__ void build_il_kernel(const float* __restrict__ L,
                                const float* __restrict__ P) {
    int idx = blockIdx.x * blockDim.x + threadIdx.x;
    // generators: 3*2*16*32 = 3072 float4
    if (idx < DC * 2 * 16 * 32) {
        int l   = idx & 31;
        int q   = (idx >> 5) & 15;
        int rr  = (idx >> 9) & 1;
        int g   = idx >> 10;
        int row = l + 32 * rr;
        float4 v;
        const float* Lg = L + g * DH * DH;
        int c0 = 4 * q;
        v.x = 0.5f * (Lg[row * DH + c0 + 0] - Lg[(c0 + 0) * DH + row]);
        v.y = 0.5f * (Lg[row * DH + c0 + 1] - Lg[(c0 + 1) * DH + row]);
        v.z = 0.5f * (Lg[row * DH + c0 + 2] - Lg[(c0 + 2) * DH + row]);
        v.w = 0.5f * (Lg[row * DH + c0 + 3] - Lg[(c0 + 3) * DH + row]);
        g_skew_il[idx] = v;
    }
    // P_sp: 2*16*32 = 1024 float4
    int pidx = idx - DC * 2 * 16 * 32;
    if (pidx >= 0 && pidx < 2 * 16 * 32) {
        int l   = pidx & 31;
        int q   = (pidx >> 5) & 15;
        int rr  = (pidx >> 9) & 1;
        int row = l + 32 * rr;
        const float4* pr = reinterpret_cast<const float4*>(P + row * DH);
        g_psp_il[pidx] = pr[q];
    }
}

__global__ void gram_kernel() {
    __shared__ float red[8][6];
    int t = threadIdx.x;   // 256 threads
    float g[6] = {0.f, 0.f, 0.f, 0.f, 0.f, 0.f};
    // gen stride in float4 units = 2*16*32 = 1024
    for (int j = t; j < 1024; j += 256) {
        float4 a = g_skew_il[j];
        float4 b = g_skew_il[1024 + j];
        float4 c = g_skew_il[2048 + j];
        g[0] += a.x*a.x + a.y*a.y + a.z*a.z + a.w*a.w;
        g[1] += a.x*b.x + a.y*b.y + a.z*b.z + a.w*b.w;
        g[2] += a.x*c.x + a.y*c.y + a.z*c.z + a.w*c.w;
        g[3] += b.x*b.x + b.y*b.y + b.z*b.z + b.w*b.w;
        g[4] += b.x*c.x + b.y*c.y + b.z*c.z + b.w*c.w;
        g[5] += c.x*c.x + c.y*c.y + c.z*c.z + c.w*c.w;
    }
    #pragma unroll
    for (int off = 16; off >= 1; off >>= 1)
        #pragma unroll
        for (int i = 0; i < 6; i++)
            g[i] += __shfl_xor_sync(0xffffffffu, g[i], off);
    if ((t & 31) == 0)
        #pragma unroll
        for (int i = 0; i < 6; i++) red[t >> 5][i] = g[i];
    __syncthreads();
    if (t < 6) {
        float s = 0.f;
        #pragma unroll
        for (int w = 0; w < 8; w++) s += red[w][t];
        g_gram[t] = s;
    }
}

// ---- packed f32x2 helpers ----
__device__ __forceinline__ ull pack2(float lo, float hi) {
    float2 t = make_float2(lo, hi);
    return *reinterpret_cast<ull*>(&t);
}
__device__ __forceinline__ float2 unpack2(ull v) {
    return *reinterpret_cast<float2*>(&v);
}
__device__ __forceinline__ void ffma2(ull& d, ull a, ull b) {
    asm("fma.rn.f32x2 %0, %1, %2, %0;" : "+l"(d) : "l"(a), "l"(b));
}
__device__ __forceinline__ ull add2(ull a, ull b) {
    ull r; asm("add.rn.f32x2 %0, %1, %2;" : "=l"(r) : "l"(a), "l"(b));
    return r;
}

// Full-row matvec: lane owns rows l and l+32 over all 64 columns.
__device__ __forceinline__ void matvec_fr(const ull* A0, const ull* A1,
                                          const float* v,
                                          float& o0, float& o1)
{
    const ulonglong2* vv = reinterpret_cast<const ulonglong2*>(v);
    ull a0[4] = {0ull, 0ull, 0ull, 0ull};
    ull a1[4] = {0ull, 0ull, 0ull, 0ull};
    #pragma unroll
    for (int q = 0; q < 16; q++) {
        ulonglong2 t = vv[q];
        ffma2(a0[(2 * q)     & 3], A0[2 * q],     t.x);
        ffma2(a0[(2 * q + 1) & 3], A0[2 * q + 1], t.y);
        ffma2(a1[(2 * q)     & 3], A1[2 * q],     t.x);
        ffma2(a1[(2 * q + 1) & 3], A1[2 * q + 1], t.y);
    }
    float2 f0 = unpack2(add2(add2(a0[0], a0[1]), add2(a0[2], a0[3])));
    o0 = f0.x + f0.y;
    float2 f1 = unpack2(add2(add2(a1[0], a1[1]), add2(a1[2], a1[3])));
    o1 = f1.x + f1.y;
}

// One Chebyshev term with compile-time buffer indices.
template <int B1, int B2, int BF>
__device__ __forceinline__ void cheb_iter(
    float (*sv)[DH], const ull* A0, const ull* A1, const float* scoef,
    float& y0, float& y1, int kk, int l)
{
    float old0 = sv[B2][l];
    float old1 = sv[B2][l + 32];
    float o0, o1;
    matvec_fr(A0, A1, sv[B1], o0, o1);
    float cf = scoef[kk];
    float pn0 = o0 + old0;
    float pn1 = o1 + old1;
    y0 = fmaf(cf, pn0, y0);
    y1 = fmaf(cf, pn1, y1);
    sv[BF][l]      = pn0;
    sv[BF][l + 32] = pn1;
    __syncwarp();
}

__global__ __launch_bounds__(32, 11)
void liepe_expmv_kernel(const float* __restrict__ x,
                        const float* __restrict__ rg,
                        float* __restrict__ out)
{
    __shared__ __align__(16) float sv[3][DH];
    __shared__ float scoef[64];

    const int l = threadIdx.x;
    const int pos = blockIdx.x;

    const float r0 = __ldg(&rg[pos * DC + 0]);
    const float r1 = __ldg(&rg[pos * DC + 1]);
    const float r2 = __ldg(&rg[pos * DC + 2]);

    // ---- rho from generator Gram matrix: ||A||_F^2 = r' G r ----
    float rho;
    {
        float g0 = __ldg(&g_gram[0]), g1 = __ldg(&g_gram[1]);
        float g2 = __ldg(&g_gram[2]), g3 = __ldg(&g_gram[3]);
        float g4 = __ldg(&g_gram[4]), g5 = __ldg(&g_gram[5]);
        float F2 = r0 * r0 * g0 + r1 * r1 * g3 + r2 * r2 * g5
                 + 2.0f * (r0 * r1 * g1 + r0 * r2 * g2 + r1 * r2 * g4);
        rho = 0.335f * sqrtf(fmaxf(F2, 0.f));   // 0.25 edge * 1.34 safety
        rho = fmaxf(rho, 0.5f);
    }
    int kmax = (int)ceilf(rho) + 9;
    if (kmax > 48) kmax = 48;
    const float inv_rho = 1.0f / rho;

    // ---- Bessel coefficients J_k(rho) via Miller downward (A not yet live) ----
    {
        int K = kmax + 10;
        float jp = 0.f, jc = 1e-25f;
        float s = 0.f, c1 = 0.f, c2 = 0.f;
        for (int kk = K; kk >= 1; kk--) {
            float jm = fmaf(2.0f * (float)kk * inv_rho, jc, -jp); // J_{kk-1}
            int km1 = kk - 1;
            if (km1 == l)      c1 = jm;
            if (km1 == l + 32) c2 = jm;
            if (km1 == 0)            s += jm;
            else if ((km1 & 1) == 0) s += 2.0f * jm;
            if (fabsf(jm) > 1e24f) {
                jm *= 1e-24f; jc *= 1e-24f; s *= 1e-24f;
                c1 *= 1e-24f; c2 *= 1e-24f;
            }
            jp = jc; jc = jm;
        }
        float invs = 1.0f / s;     // J0 + 2*sum_{even>=2} J_k = 1
        scoef[l]      = ((l == 0) ? 1.0f : 2.0f) * c1 * invs;
        scoef[l + 32] = 2.0f * c2 * invs;
    }

    // ---- stage x ----
    sv[0][l]      = x[pos * DH + l];
    sv[0][l + 32] = x[pos * DH + 32 + l];
    __syncwarp();

    // ---- e = P_sp @ x : interleaved (coalesced) P reads ----
    float e0, e1;
    {
        const float4* vq4 = reinterpret_cast<const float4*>(sv[0]);
        float d0 = 0.f, d1 = 0.f;
        #pragma unroll
        for (int q = 0; q < 16; q++) {
            float4 vq = vq4[q];
            float4 p0 = __ldg(&g_psp_il[(0 * 16 + q) * 32 + l]);
            float4 p1 = __ldg(&g_psp_il[(1 * 16 + q) * 32 + l]);
            d0 = fmaf(p0.x, vq.x, fmaf(p0.y, vq.y,
                 fmaf(p0.z, vq.z, fmaf(p0.w, vq.w, d0))));
            d1 = fmaf(p1.x, vq.x, fmaf(p1.y, vq.y,
                 fmaf(p1.z, vq.z, fmaf(p1.w, vq.w, d1))));
        }
        e0 = d0; e1 = d1;
    }
    __syncwarp();
    sv[0][l]      = e0;
    sv[0][l + 32] = e1;
    __syncwarp();

    // ---- build C = (2/rho)*A rows l and l+32, interleaved (coalesced) reads ----
    ull A0[32], A1[32];
    {
        const float cs = 2.0f * inv_rho;
        const float c0 = r0 * cs, c1f = r1 * cs, c2f = r2 * cs;
        #pragma unroll
        for (int rr = 0; rr < 2; rr++) {
            ull* Ad = rr ? A1 : A0;
            #pragma unroll
            for (int q = 0; q < 16; q++) {
                int base = (rr * 16 + q) * 32 + l;
                float4 v0 = __ldg(&g_skew_il[base]);
                float4 v1 = __ldg(&g_skew_il[1024 + base]);
                float4 v2 = __ldg(&g_skew_il[2048 + base]);
                float ax = fmaf(c2f, v2.x, fmaf(c1f, v1.x, c0 * v0.x));
                float ay = fmaf(c2f, v2.y, fmaf(c1f, v1.y, c0 * v0.y));
                float az = fmaf(c2f, v2.z, fmaf(c1f, v1.z, c0 * v0.z));
                float aw = fmaf(c2f, v2.w, fmaf(c1f, v1.w, c0 * v0.w));
                Ad[2 * q]     = pack2(ax, ay);
                Ad[2 * q + 1] = pack2(az, aw);
            }
        }
    }

    // ---- y = coef0*phi0; phi1 = 0.5*C*phi0 -> sv[1] ----
    float cf0 = scoef[0];
    float y0 = cf0 * e0, y1 = cf0 * e1;
    {
        float o0, o1;
        matvec_fr(A0, A1, sv[0], o0, o1);
        float cf1 = scoef[1];
        float p10 = 0.5f * o0;
        float p11 = 0.5f * o1;
        y0 = fmaf(cf1, p10, y0);
        y1 = fmaf(cf1, p11, y1);
        sv[1][l]      = p10;
        sv[1][l + 32] = p11;
        __syncwarp();
    }

    // ---- Chebyshev loop, unrolled by 3 with constant buffer indices ----
    {
        int kk = 2;
        while (kk <= kmax) {
            cheb_iter<1, 0, 2>(sv, A0, A1, scoef, y0, y1, kk, l);
            if (++kk > kmax) break;
            cheb_iter<2, 1, 0>(sv, A0, A1, scoef, y0, y1, kk, l);
            if (++kk > kmax) break;
            cheb_iter<0, 2, 1>(sv, A0, A1, scoef, y0, y1, kk, l);
            ++kk;
        }
    }

    out[pos * DH + l]      = y0;
    out[pos * DH + l + 32] = y1;
}

extern "C" void kernel_launch(void* const* d_in, const int* in_sizes, int n_in,
                              void* d_out, int out_size)
{
    const float* x = (const float*)d_in[0];   // [B,S,64]
    const float* r = (const float*)d_in[1];   // [B,S,3]
    const float* L = (const float*)d_in[2];   // [3,64,64]
    const float* P = (const float*)d_in[3];   // [64,64]
    float* out = (float*)d_out;

    int npos = in_sizes[0] / DH;              // B*S
    int il_total = DC * 2 * 16 * 32 + 2 * 16 * 32;   // 4096 float4 slots

    build_il_kernel<<<(il_total + 255) / 256, 256>>>(L, P);
    gram_kernel<<<1, 256>>>();
    liepe_expmv_kernel<<<npos, 32>>>(x, r, out);
}